// round 13
// baseline (speedup 1.0000x reference)
#include <cuda_runtime.h>
#include <cuda_fp16.h>
#include <stdint.h>
#include <math.h>

// ---------------------------------------------------------------------------
// Problem dims
// ---------------------------------------------------------------------------
namespace {
constexpr int Bsz  = 16;
constexpr int Ssz  = 2048;
constexpr int Hsz  = 1024;
constexpr int INsz = 1024;
constexpr int Msz  = Bsz * Ssz;       // 32768
constexpr int NG   = 1024;
constexpr int STAGE_BYTES = 49152;    // 16KB A + 32KB B per stage
constexpr int GEMM_SMEM = 3 * STAGE_BYTES;  // 144 KiB, 3-stage ring, 1 CTA/SM
constexpr int NC   = 32;              // scan chunks
constexpr int CL   = Ssz / NC;        // 64 timesteps per chunk
}

// ---------------------------------------------------------------------------
// Scratch (__device__ globals; no allocation allowed)
// ---------------------------------------------------------------------------
__device__ float g_I[(size_t)Msz * Hsz];                   // 128 MiB
__device__ __half g_xa[(size_t)Msz * INsz];                // x 2-way fp16 split
__device__ __half g_xb[(size_t)Msz * INsz];
__device__ __half g_c1[(size_t)Msz * 2 * Hsz];             // [M][2048]: v | s
__device__ __half g_Wi1[(size_t)Hsz * INsz];               // W_in^T fp16 splits [N][K]
__device__ __half g_Wi2[(size_t)Hsz * INsz];
__device__ __half g_Wo1[(size_t)Hsz * 2 * Hsz];            // W_out^T fp16 [N][2048]
// scan pipeline scratch: [c][b][h]
__device__ float g_vend [(size_t)NC * Bsz * Hsz];
__device__ float g_vinit[(size_t)NC * Bsz * Hsz];
__device__ int   g_fc   [(size_t)NC * Bsz * Hsz];
__device__ float g_ls   [(size_t)NC * Bsz * Hsz];
__device__ float g_sinit[(size_t)NC * Bsz * Hsz];

// ---------------------------------------------------------------------------
// PTX helpers (base sm_80+ features only)
// ---------------------------------------------------------------------------
#define SWZ128(o) ((o) ^ (((o) >> 3) & 0x70))

__device__ __forceinline__ uint32_t smem_u32(const void* p) {
    uint32_t a;
    asm("{ .reg .u64 t; cvta.to.shared.u64 t, %1; cvt.u32.u64 %0, t; }"
        : "=r"(a) : "l"(p));
    return a;
}
#define CP_ASYNC16(s, g) \
    asm volatile("cp.async.cg.shared.global [%0], [%1], 16;" :: "r"(s), "l"(g))
#define CP_COMMIT()  asm volatile("cp.async.commit_group;" ::: "memory")
#define CP_WAIT0()   asm volatile("cp.async.wait_group 0;" ::: "memory")
#define CP_WAIT1()   asm volatile("cp.async.wait_group 1;" ::: "memory")

__device__ __forceinline__ void ldsm_x4(uint32_t r[4], uint32_t addr) {
    asm volatile("ldmatrix.sync.aligned.m8n8.x4.shared.b16 {%0,%1,%2,%3}, [%4];"
        : "=r"(r[0]), "=r"(r[1]), "=r"(r[2]), "=r"(r[3]) : "r"(addr));
}
__device__ __forceinline__ void mma_fp16(float c[4], const uint32_t a[4],
                                         const uint32_t b[2]) {
    asm volatile(
        "mma.sync.aligned.m16n8k16.row.col.f32.f16.f16.f32 "
        "{%0,%1,%2,%3}, {%4,%5,%6,%7}, {%8,%9}, {%0,%1,%2,%3};"
        : "+f"(c[0]), "+f"(c[1]), "+f"(c[2]), "+f"(c[3])
        : "r"(a[0]), "r"(a[1]), "r"(a[2]), "r"(a[3]), "r"(b[0]), "r"(b[1]));
}

// ---------------------------------------------------------------------------
// Split kernels (fp16 2-way), vectorized
// ---------------------------------------------------------------------------
__global__ void split2_x(const float4* __restrict__ x4, __half2* __restrict__ o1,
                         __half2* __restrict__ o2, size_t n4)
{
    size_t i = (size_t)blockIdx.x * blockDim.x + threadIdx.x;
    size_t stride = (size_t)gridDim.x * blockDim.x;
    for (; i < n4; i += stride) {
        float4 w = x4[i];
        __half a0 = __float2half_rn(w.x), a1 = __float2half_rn(w.y);
        __half a2 = __float2half_rn(w.z), a3 = __float2half_rn(w.w);
        o1[2 * i]     = __halves2half2(a0, a1);
        o1[2 * i + 1] = __halves2half2(a2, a3);
        o2[2 * i]     = __halves2half2(
            __float2half_rn(w.x - __half2float(a0)),
            __float2half_rn(w.y - __half2float(a1)));
        o2[2 * i + 1] = __halves2half2(
            __float2half_rn(w.z - __half2float(a2)),
            __float2half_rn(w.w - __half2float(a3)));
    }
}

// W[K][N] fp32 -> o[N][K] fp16 2-way split (o2 optional)
__global__ void transpose_split2(const float* __restrict__ W, int K, int N,
                                 __half* __restrict__ o1,
                                 __half* __restrict__ o2)
{
    __shared__ float t[32][33];
    int n0 = blockIdx.x * 32, k0 = blockIdx.y * 32;
    int tx = threadIdx.x, ty = threadIdx.y;   // (32, 8)
#pragma unroll
    for (int i = 0; i < 4; ++i)
        t[ty + i * 8][tx] = W[(size_t)(k0 + ty + i * 8) * N + n0 + tx];
    __syncthreads();
#pragma unroll
    for (int i = 0; i < 4; ++i) {
        int nn = n0 + ty + i * 8, k = k0 + tx;
        float w = t[tx][ty + i * 8];
        __half a = __float2half_rn(w);
        o1[(size_t)nn * K + k] = a;
        if (o2) {
            float r = w - __half2float(a);
            o2[(size_t)nn * K + k] = __float2half_rn(r);
        }
    }
}

// ---------------------------------------------------------------------------
// Chunked parallel hysteresis scan (proven in R8).
// ---------------------------------------------------------------------------
__device__ __forceinline__ float sig_alpha(const float* lt, int h) {
    return 1.0f / (1.0f + expf(lt[h]));
}

__global__ void scan_s1(const float* __restrict__ leak_tau)
{
    const int h = blockIdx.x * blockDim.x + threadIdx.x;
    const int b = blockIdx.y, c = blockIdx.z;
    const float alpha = sig_alpha(leak_tau, h);
    const float* Ip = g_I + ((size_t)b * Ssz + c * CL) * Hsz + h;
    float v = 0.0f;
#pragma unroll 4
    for (int t = 0; t < CL; ++t)
        v = fmaf(alpha, v, Ip[(size_t)t * Hsz]);
    g_vend[((size_t)c * Bsz + b) * Hsz + h] = v;
}

__global__ void scan_s2(const float* __restrict__ leak_tau)
{
    const int h = blockIdx.x * blockDim.x + threadIdx.x;
    const int b = blockIdx.y;
    const float alpha = sig_alpha(leak_tau, h);
    const float aL = powf(alpha, (float)CL);
    float v = 0.0f;
    for (int c = 0; c < NC; ++c) {
        size_t o = ((size_t)c * Bsz + b) * Hsz + h;
        g_vinit[o] = v;
        v = fmaf(aL, v, g_vend[o]);
    }
}

__global__ void scan_s3(const float* __restrict__ leak_tau,
                        const float* __restrict__ thr_arr)
{
    const int h = blockIdx.x * blockDim.x + threadIdx.x;
    const int b = blockIdx.y, c = blockIdx.z;
    const float alpha = sig_alpha(leak_tau, h);
    const float th = thr_arr[h];
    const size_t co = ((size_t)c * Bsz + b) * Hsz + h;
    float v = g_vinit[co];

    const int t0 = c * CL;
    const float* Ip = g_I + ((size_t)b * Ssz + t0) * Hsz + h;
    __half* c1 = g_c1 + ((size_t)b * Ssz + t0) * 2 * Hsz + h;

    int fc = CL;
    float s = 0.0f;
#pragma unroll 4
    for (int t = 0; t < CL; ++t) {
        v = fmaf(alpha, v, Ip[(size_t)t * Hsz]);
        bool up = v > th, dn = v < -th;
        if (up | dn) {
            if (fc == CL) fc = t;
            s = up ? 1.0f : -1.0f;
        }
        c1[(size_t)t * 2 * Hsz] = __float2half_rn(v);
        if (fc != CL)
            c1[(size_t)t * 2 * Hsz + Hsz] = __float2half_rn(s);
    }
    g_fc[co] = fc;
    g_ls[co] = s;
}

__global__ void scan_s4()
{
    const int h = blockIdx.x * blockDim.x + threadIdx.x;
    const int b = blockIdx.y;
    float s = -1.0f;
    for (int c = 0; c < NC; ++c) {
        size_t o = ((size_t)c * Bsz + b) * Hsz + h;
        g_sinit[o] = s;
        if (g_fc[o] < CL) s = g_ls[o];
    }
}

__global__ void scan_s5()
{
    const int h = blockIdx.x * blockDim.x + threadIdx.x;
    const int b = blockIdx.y, c = blockIdx.z;
    const size_t co = ((size_t)c * Bsz + b) * Hsz + h;
    const int fc = g_fc[co];
    if (fc == 0) return;
    const __half sv = __float2half_rn(g_sinit[co]);
    __half* c1s = g_c1 + ((size_t)b * Ssz + c * CL) * 2 * Hsz + Hsz + h;
    for (int t = 0; t < fc; ++t)
        c1s[(size_t)t * 2 * Hsz] = sv;
}

// ---------------------------------------------------------------------------
// Multi-phase fp16 split-GEMM on mma.sync.
// CTA tile 128(M) x 256(N), 8 warps (2x4), WARP TILE 64x64 (acc 128 regs,
// 1 CTA/SM). LDSM/HMMA = 0.25 (was 0.375). 3-stage 48KB ring, one barrier
// per K-iter (proven R6 order: wait -> barrier -> issue(it+2) -> compute).
// ---------------------------------------------------------------------------
struct GemmSpec {
    const __half* A[3];
    const __half* B[3];
    int lda[3];
    int ldb[3];
    int cum[4];
};

template<int NPH, int T, bool DO_TANH>
__global__ __launch_bounds__(256, 1)
void gemm_mma(const __grid_constant__ GemmSpec spec,
              const float* __restrict__ bias, float* __restrict__ C)
{
    extern __shared__ __align__(1024) char smem[];
    const uint32_t sb = smem_u32(smem);
    const int tid = threadIdx.x, lane = tid & 31, wid = tid >> 5;
    const int wm = wid >> 2, wn = wid & 3;          // 2 (M) x 4 (N)
    const int m0 = blockIdx.y * 128, n0 = blockIdx.x * 256;

    float acc[4][8][4];
#pragma unroll
    for (int i = 0; i < 4; ++i)
#pragma unroll
        for (int j = 0; j < 8; ++j)
#pragma unroll
            for (int k = 0; k < 4; ++k) acc[i][j][k] = 0.0f;

    // Hoisted LDSM addressing: offset = row*128 + (col ^ ((row&7)<<4)).
    uint32_t aBase[4], aXm;
    {
        int r0 = wm * 64 + (lane & 15);
#pragma unroll
        for (int mt = 0; mt < 4; ++mt) aBase[mt] = (uint32_t)((r0 + mt * 16) * 128);
        aXm = (uint32_t)(((r0 & 7) << 4));
    }
    const uint32_t aCol0 = (uint32_t)((lane >> 4) * 16);
    // B: 4 pairwise-x4 groups cover 8 n-tiles of warp's 64-wide N range.
    uint32_t bBase[4], bXm;
    {
        int mat = lane >> 3;
        int rb = wn * 64 + (mat >> 1) * 8 + (lane & 7);
#pragma unroll
        for (int np = 0; np < 4; ++np) bBase[np] = (uint32_t)((rb + np * 16) * 128);
        bXm = (uint32_t)(((rb & 7) << 4));
    }
    const uint32_t bCol0 = (uint32_t)(((lane >> 3) & 1) * 16);

    auto issue_loads = [&](int it) {
        int ph = 0;
#pragma unroll
        for (int p = 0; p < NPH - 1; ++p) if (it >= spec.cum[p + 1]) ph = p + 1;
        const int kt = (it - spec.cum[ph]) * 64;
        const int lda = spec.lda[ph], ldb = spec.ldb[ph];
        const char* Apc = (const char*)spec.A[ph];
        const char* Bpc = (const char*)spec.B[ph];
        const uint32_t sA = sb + (it % 3) * STAGE_BYTES;
        const uint32_t sB = sA + 16384;
        // A tile: 128 rows x 128B = 4 cp.async/thread
#pragma unroll
        for (int i = 0; i < 4; ++i) {
            int id = tid + 256 * i;
            int r = id >> 3, cb = (id & 7) * 16;
            CP_ASYNC16(sA + SWZ128(r * 128 + cb),
                       Apc + ((size_t)(m0 + r) * lda + kt) * 2 + cb);
        }
        // B tile: 256 rows x 128B = 8 cp.async/thread
#pragma unroll
        for (int i = 0; i < 8; ++i) {
            int id = tid + 256 * i;
            int r = id >> 3, cb = (id & 7) * 16;
            CP_ASYNC16(sB + SWZ128(r * 128 + cb),
                       Bpc + ((size_t)(n0 + r) * ldb + kt) * 2 + cb);
        }
    };

    issue_loads(0); CP_COMMIT();
    issue_loads(1); CP_COMMIT();

#pragma unroll 1
    for (int it = 0; it < T; ++it) {
        if (it + 1 < T) { CP_WAIT1(); } else { CP_WAIT0(); }
        __syncthreads();
        if (it + 2 < T) { issue_loads(it + 2); CP_COMMIT(); }

        const uint32_t sA = sb + (it % 3) * STAGE_BYTES;
        const uint32_t sB = sA + 16384;
#pragma unroll
        for (int kk = 0; kk < 4; ++kk) {
            uint32_t aF[4][4], bF[8][2];
            const uint32_t aCol = ((uint32_t)(kk * 32) + aCol0) ^ aXm;
            const uint32_t bCol = ((uint32_t)(kk * 32) + bCol0) ^ bXm;
#pragma unroll
            for (int mt = 0; mt < 4; ++mt)
                ldsm_x4(aF[mt], sA + aBase[mt] + aCol);
#pragma unroll
            for (int np = 0; np < 4; ++np) {
                uint32_t r4[4];
                ldsm_x4(r4, sB + bBase[np] + bCol);
                bF[2 * np][0] = r4[0]; bF[2 * np][1] = r4[1];
                bF[2 * np + 1][0] = r4[2]; bF[2 * np + 1][1] = r4[3];
            }
#pragma unroll
            for (int mt = 0; mt < 4; ++mt)
#pragma unroll
                for (int nt = 0; nt < 8; ++nt)
                    mma_fp16(acc[mt][nt], aF[mt], bF[nt]);
        }
    }

    const int gid = lane >> 2, tig = lane & 3;
#pragma unroll
    for (int mt = 0; mt < 4; ++mt) {
#pragma unroll
        for (int nt = 0; nt < 8; ++nt) {
            int col = n0 + wn * 64 + nt * 8 + 2 * tig;
            float2 bv = *reinterpret_cast<const float2*>(&bias[col]);
            int r0 = m0 + wm * 64 + mt * 16 + gid;
            float2 v0, v1;
            v0.x = acc[mt][nt][0] + bv.x; v0.y = acc[mt][nt][1] + bv.y;
            v1.x = acc[mt][nt][2] + bv.x; v1.y = acc[mt][nt][3] + bv.y;
            if (DO_TANH) {
                v0.x = tanhf(v0.x); v0.y = tanhf(v0.y);
                v1.x = tanhf(v1.x); v1.y = tanhf(v1.y);
            }
            *reinterpret_cast<float2*>(&C[(size_t)r0 * NG + col]) = v0;
            *reinterpret_cast<float2*>(&C[(size_t)(r0 + 8) * NG + col]) = v1;
        }
    }
}

// ---------------------------------------------------------------------------
extern "C" void kernel_launch(void* const* d_in, const int* in_sizes, int n_in,
                              void* d_out, int out_size)
{
    const float* x        = (const float*)d_in[0];
    const float* W_in     = (const float*)d_in[1];
    const float* b_in     = (const float*)d_in[2];
    const float* leak_tau = (const float*)d_in[3];
    const float* thr      = (const float*)d_in[4];
    const float* W_out    = (const float*)d_in[5];
    const float* b_out    = (const float*)d_in[6];
    float* out = (float*)d_out;

    float* pI; cudaGetSymbolAddress((void**)&pI, g_I);
    __half *xa, *xb, *c1, *Wi1, *Wi2, *Wo1;
    cudaGetSymbolAddress((void**)&xa,  g_xa);
    cudaGetSymbolAddress((void**)&xb,  g_xb);
    cudaGetSymbolAddress((void**)&c1,  g_c1);
    cudaGetSymbolAddress((void**)&Wi1, g_Wi1);
    cudaGetSymbolAddress((void**)&Wi2, g_Wi2);
    cudaGetSymbolAddress((void**)&Wo1, g_Wo1);

    cudaFuncSetAttribute(gemm_mma<3, 48, false>,
                         cudaFuncAttributeMaxDynamicSharedMemorySize, GEMM_SMEM);
    cudaFuncSetAttribute(gemm_mma<1, 32, true>,
                         cudaFuncAttributeMaxDynamicSharedMemorySize, GEMM_SMEM);

    // Splits (fp16 2-way; W_out only needs the primary fp16 image)
    split2_x<<<2048, 256>>>((const float4*)x, (__half2*)xa, (__half2*)xb,
                            (size_t)Msz * INsz / 4);
    transpose_split2<<<dim3(Hsz / 32, INsz / 32), dim3(32, 8)>>>(
        W_in, INsz, Hsz, Wi1, Wi2);
    transpose_split2<<<dim3(Hsz / 32, (2 * Hsz) / 32), dim3(32, 8)>>>(
        W_out, 2 * Hsz, Hsz, Wo1, nullptr);

    // GEMM1: I = x @ W_in + b_in — 3-term fp16 split, small terms first:
    //   (2,1) xb*Wi1, (1,2) xa*Wi2, (1,1) xa*Wi1  (16 iters each)
    //   (Pre-threshold: residual terms REQUIRED — flip amplification.)
    {
        GemmSpec g = {};
        const __half* As[3] = { xb,  xa,  xa  };
        const __half* Bs[3] = { Wi1, Wi2, Wi1 };
        for (int p = 0; p < 3; ++p) {
            g.A[p] = As[p]; g.B[p] = Bs[p];
            g.lda[p] = INsz; g.ldb[p] = INsz;
            g.cum[p] = p * 16;
        }
        g.cum[3] = 48;
        gemm_mma<3, 48, false><<<dim3(Hsz / 256, Msz / 128), 256, GEMM_SMEM>>>(
            g, b_in, pI);
    }

    // Chunked parallel scan -> c1
    {
        dim3 gc(Hsz / 256, Bsz, NC);
        dim3 gs(Hsz / 256, Bsz, 1);
        scan_s1<<<gc, 256>>>(leak_tau);
        scan_s2<<<gs, 256>>>(leak_tau);
        scan_s3<<<gc, 256>>>(leak_tau, thr);
        scan_s4<<<gs, 256>>>();
        scan_s5<<<gc, 256>>>();
    }

    // GEMM2: out = tanh(c1 @ Wo1^T + b_out) — single plain fp16 GEMM
    // (both residual terms dropped; calibrated post-trigger error calculus).
    {
        GemmSpec g = {};
        g.A[0] = c1; g.B[0] = Wo1; g.lda[0] = 2048; g.ldb[0] = 2048;
        g.A[1] = c1; g.B[1] = Wo1; g.lda[1] = 2048; g.ldb[1] = 2048; // unused
        g.A[2] = c1; g.B[2] = Wo1; g.lda[2] = 2048; g.ldb[2] = 2048; // unused
        g.cum[0] = 0; g.cum[1] = 32; g.cum[2] = 32; g.cum[3] = 32;
        gemm_mma<1, 32, true><<<dim3(NG / 256, Msz / 128), 256, GEMM_SMEM>>>(
            g, b_out, out);
    }
}

// round 14
// speedup vs baseline: 1.0764x; 1.0764x over previous
#include <cuda_runtime.h>
#include <cuda_fp16.h>
#include <stdint.h>
#include <math.h>

// ---------------------------------------------------------------------------
// Problem dims
// ---------------------------------------------------------------------------
namespace {
constexpr int Bsz  = 16;
constexpr int Ssz  = 2048;
constexpr int Hsz  = 1024;
constexpr int INsz = 1024;
constexpr int Msz  = Bsz * Ssz;       // 32768
constexpr int NG   = 1024;
constexpr int STAGE_BYTES = 32768;    // 16KB A + 16KB B per stage
constexpr int GEMM_SMEM = 3 * STAGE_BYTES;  // 96 KiB, 3-stage ring, 2 CTA/SM
constexpr int NC   = 32;              // scan chunks
constexpr int CL   = Ssz / NC;        // 64 timesteps per chunk
}

// ---------------------------------------------------------------------------
// Scratch (__device__ globals; no allocation allowed)
// ---------------------------------------------------------------------------
__device__ float g_I[(size_t)Msz * Hsz];                   // 128 MiB
__device__ __half g_xa[(size_t)Msz * INsz];                // x 2-way fp16 split
__device__ __half g_xb[(size_t)Msz * INsz];
__device__ __half g_c1[(size_t)Msz * 2 * Hsz];             // [M][2048]: v | s
__device__ __half g_Wi1[(size_t)Hsz * INsz];               // W_in^T fp16 splits [N][K]
__device__ __half g_Wi2[(size_t)Hsz * INsz];
__device__ __half g_Wo1[(size_t)Hsz * 2 * Hsz];            // W_out^T fp16 [N][2048]
// scan pipeline scratch: [c][b][h]
__device__ float g_vend [(size_t)NC * Bsz * Hsz];
__device__ float g_vinit[(size_t)NC * Bsz * Hsz];
__device__ int   g_fc   [(size_t)NC * Bsz * Hsz];
__device__ float g_ls   [(size_t)NC * Bsz * Hsz];
__device__ float g_sinit[(size_t)NC * Bsz * Hsz];

// ---------------------------------------------------------------------------
// PTX helpers (base sm_80+ features only)
// ---------------------------------------------------------------------------
#define SWZ128(o) ((o) ^ (((o) >> 3) & 0x70))

__device__ __forceinline__ uint32_t smem_u32(const void* p) {
    uint32_t a;
    asm("{ .reg .u64 t; cvta.to.shared.u64 t, %1; cvt.u32.u64 %0, t; }"
        : "=r"(a) : "l"(p));
    return a;
}
#define CP_ASYNC16(s, g) \
    asm volatile("cp.async.cg.shared.global [%0], [%1], 16;" :: "r"(s), "l"(g))
#define CP_COMMIT()  asm volatile("cp.async.commit_group;" ::: "memory")
#define CP_WAIT0()   asm volatile("cp.async.wait_group 0;" ::: "memory")
#define CP_WAIT1()   asm volatile("cp.async.wait_group 1;" ::: "memory")

__device__ __forceinline__ void ldsm_x4(uint32_t r[4], uint32_t addr) {
    asm volatile("ldmatrix.sync.aligned.m8n8.x4.shared.b16 {%0,%1,%2,%3}, [%4];"
        : "=r"(r[0]), "=r"(r[1]), "=r"(r[2]), "=r"(r[3]) : "r"(addr));
}
__device__ __forceinline__ void mma_fp16(float c[4], const uint32_t a[4],
                                         const uint32_t b[2]) {
    asm volatile(
        "mma.sync.aligned.m16n8k16.row.col.f32.f16.f16.f32 "
        "{%0,%1,%2,%3}, {%4,%5,%6,%7}, {%8,%9}, {%0,%1,%2,%3};"
        : "+f"(c[0]), "+f"(c[1]), "+f"(c[2]), "+f"(c[3])
        : "r"(a[0]), "r"(a[1]), "r"(a[2]), "r"(a[3]), "r"(b[0]), "r"(b[1]));
}

// ---------------------------------------------------------------------------
// Split kernels (fp16 2-way), vectorized
// ---------------------------------------------------------------------------
__global__ void split2_x(const float4* __restrict__ x4, __half2* __restrict__ o1,
                         __half2* __restrict__ o2, size_t n4)
{
    size_t i = (size_t)blockIdx.x * blockDim.x + threadIdx.x;
    size_t stride = (size_t)gridDim.x * blockDim.x;
    for (; i < n4; i += stride) {
        float4 w = x4[i];
        __half a0 = __float2half_rn(w.x), a1 = __float2half_rn(w.y);
        __half a2 = __float2half_rn(w.z), a3 = __float2half_rn(w.w);
        o1[2 * i]     = __halves2half2(a0, a1);
        o1[2 * i + 1] = __halves2half2(a2, a3);
        o2[2 * i]     = __halves2half2(
            __float2half_rn(w.x - __half2float(a0)),
            __float2half_rn(w.y - __half2float(a1)));
        o2[2 * i + 1] = __halves2half2(
            __float2half_rn(w.z - __half2float(a2)),
            __float2half_rn(w.w - __half2float(a3)));
    }
}

// W[K][N] fp32 -> o[N][K] fp16 2-way split (o2 optional)
__global__ void transpose_split2(const float* __restrict__ W, int K, int N,
                                 __half* __restrict__ o1,
                                 __half* __restrict__ o2)
{
    __shared__ float t[32][33];
    int n0 = blockIdx.x * 32, k0 = blockIdx.y * 32;
    int tx = threadIdx.x, ty = threadIdx.y;   // (32, 8)
#pragma unroll
    for (int i = 0; i < 4; ++i)
        t[ty + i * 8][tx] = W[(size_t)(k0 + ty + i * 8) * N + n0 + tx];
    __syncthreads();
#pragma unroll
    for (int i = 0; i < 4; ++i) {
        int nn = n0 + ty + i * 8, k = k0 + tx;
        float w = t[tx][ty + i * 8];
        __half a = __float2half_rn(w);
        o1[(size_t)nn * K + k] = a;
        if (o2) {
            float r = w - __half2float(a);
            o2[(size_t)nn * K + k] = __float2half_rn(r);
        }
    }
}

// ---------------------------------------------------------------------------
// Chunked parallel hysteresis scan (proven in R8).
// ---------------------------------------------------------------------------
__device__ __forceinline__ float sig_alpha(const float* lt, int h) {
    return 1.0f / (1.0f + expf(lt[h]));
}

__global__ void scan_s1(const float* __restrict__ leak_tau)
{
    const int h = blockIdx.x * blockDim.x + threadIdx.x;
    const int b = blockIdx.y, c = blockIdx.z;
    const float alpha = sig_alpha(leak_tau, h);
    const float* Ip = g_I + ((size_t)b * Ssz + c * CL) * Hsz + h;
    float v = 0.0f;
#pragma unroll 4
    for (int t = 0; t < CL; ++t)
        v = fmaf(alpha, v, Ip[(size_t)t * Hsz]);
    g_vend[((size_t)c * Bsz + b) * Hsz + h] = v;
}

__global__ void scan_s2(const float* __restrict__ leak_tau)
{
    const int h = blockIdx.x * blockDim.x + threadIdx.x;
    const int b = blockIdx.y;
    const float alpha = sig_alpha(leak_tau, h);
    const float aL = powf(alpha, (float)CL);
    float v = 0.0f;
    for (int c = 0; c < NC; ++c) {
        size_t o = ((size_t)c * Bsz + b) * Hsz + h;
        g_vinit[o] = v;
        v = fmaf(aL, v, g_vend[o]);
    }
}

__global__ void scan_s3(const float* __restrict__ leak_tau,
                        const float* __restrict__ thr_arr)
{
    const int h = blockIdx.x * blockDim.x + threadIdx.x;
    const int b = blockIdx.y, c = blockIdx.z;
    const float alpha = sig_alpha(leak_tau, h);
    const float th = thr_arr[h];
    const size_t co = ((size_t)c * Bsz + b) * Hsz + h;
    float v = g_vinit[co];

    const int t0 = c * CL;
    const float* Ip = g_I + ((size_t)b * Ssz + t0) * Hsz + h;
    __half* c1 = g_c1 + ((size_t)b * Ssz + t0) * 2 * Hsz + h;

    int fc = CL;
    float s = 0.0f;
#pragma unroll 4
    for (int t = 0; t < CL; ++t) {
        v = fmaf(alpha, v, Ip[(size_t)t * Hsz]);
        bool up = v > th, dn = v < -th;
        if (up | dn) {
            if (fc == CL) fc = t;
            s = up ? 1.0f : -1.0f;
        }
        c1[(size_t)t * 2 * Hsz] = __float2half_rn(v);
        if (fc != CL)
            c1[(size_t)t * 2 * Hsz + Hsz] = __float2half_rn(s);
    }
    g_fc[co] = fc;
    g_ls[co] = s;
}

__global__ void scan_s4()
{
    const int h = blockIdx.x * blockDim.x + threadIdx.x;
    const int b = blockIdx.y;
    float s = -1.0f;
    for (int c = 0; c < NC; ++c) {
        size_t o = ((size_t)c * Bsz + b) * Hsz + h;
        g_sinit[o] = s;
        if (g_fc[o] < CL) s = g_ls[o];
    }
}

__global__ void scan_s5()
{
    const int h = blockIdx.x * blockDim.x + threadIdx.x;
    const int b = blockIdx.y, c = blockIdx.z;
    const size_t co = ((size_t)c * Bsz + b) * Hsz + h;
    const int fc = g_fc[co];
    if (fc == 0) return;
    const __half sv = __float2half_rn(g_sinit[co]);
    __half* c1s = g_c1 + ((size_t)b * Ssz + c * CL) * 2 * Hsz + Hsz + h;
    for (int t = 0; t < fc; ++t)
        c1s[(size_t)t * 2 * Hsz] = sv;
}

// ---------------------------------------------------------------------------
// Multi-phase fp16 split-GEMM on mma.sync (R12 config: CTA 128x128, 8 warps
// 2x4, warp tile 64x32, 3-stage ring, 2 CTA/SM — proven optimum).
// R14 change: cp.async global/shared addresses precomputed per phase; per
// iter only a kt-byte offset add remains (alu-pipe reduction).
// ---------------------------------------------------------------------------
struct GemmSpec {
    const __half* A[3];
    const __half* B[3];
    int lda[3];
    int ldb[3];
    int cum[4];
};

template<int NPH, int T, bool DO_TANH>
__global__ __launch_bounds__(256, 2)
void gemm_mma(const __grid_constant__ GemmSpec spec,
              const float* __restrict__ bias, float* __restrict__ C)
{
    extern __shared__ __align__(1024) char smem[];
    const uint32_t sb = smem_u32(smem);
    const int tid = threadIdx.x, lane = tid & 31, wid = tid >> 5;
    const int wm = wid >> 2, wn = wid & 3;
    const int m0 = blockIdx.y * 128, n0 = blockIdx.x * 128;

    float acc[4][4][4];
#pragma unroll
    for (int i = 0; i < 4; ++i)
#pragma unroll
        for (int j = 0; j < 4; ++j)
#pragma unroll
            for (int k = 0; k < 4; ++k) acc[i][j][k] = 0.0f;

    // --- Precomputed cp.async addressing -------------------------------
    // Per-thread tile coords: row r0 = tid>>3 (+32 per i), col cb.
    const int ldr = tid >> 3;
    const int ldc = (tid & 7) * 16;
    // Smem store offset: swizzle mask depends only on r&7 (same for all i);
    // i adds exactly 32*128 = 4096 bytes.
    const uint32_t sOff = (uint32_t)SWZ128(ldr * 128 + ldc);
    // Per-phase global base pointers (bytes) + per-i row stride.
    const char* gA[NPH]; const char* gB[NPH];
    int64_t aStride[NPH], bStride[NPH];
#pragma unroll
    for (int p = 0; p < NPH; ++p) {
        gA[p] = (const char*)spec.A[p] + ((size_t)(m0 + ldr) * spec.lda[p] + 0) * 2 + ldc;
        gB[p] = (const char*)spec.B[p] + ((size_t)(n0 + ldr) * spec.ldb[p] + 0) * 2 + ldc;
        aStride[p] = (int64_t)32 * spec.lda[p] * 2;
        bStride[p] = (int64_t)32 * spec.ldb[p] * 2;
    }

    // Hoisted LDSM addressing: offset = row*128 + (col ^ ((row&7)<<4)).
    uint32_t aBase[4], aXm;
    {
        int r0 = wm * 64 + (lane & 15);
#pragma unroll
        for (int mt = 0; mt < 4; ++mt) aBase[mt] = (uint32_t)((r0 + mt * 16) * 128);
        aXm = (uint32_t)(((r0 & 7) << 4));
    }
    const uint32_t aCol0 = (uint32_t)((lane >> 4) * 16);
    uint32_t bBase[2], bXm;
    {
        int mat = lane >> 3;
        int rb = wn * 32 + (mat >> 1) * 8 + (lane & 7);
#pragma unroll
        for (int np = 0; np < 2; ++np) bBase[np] = (uint32_t)((rb + np * 16) * 128);
        bXm = (uint32_t)(((rb & 7) << 4));
    }
    const uint32_t bCol0 = (uint32_t)(((lane >> 3) & 1) * 16);

    auto issue_loads = [&](int it) {
        int ph = 0;
#pragma unroll
        for (int p = 0; p < NPH - 1; ++p) if (it >= spec.cum[p + 1]) ph = p + 1;
        const int64_t kt2 = (int64_t)(it - spec.cum[ph]) * 128;  // 64 elem * 2B
        const uint32_t sA = sb + (it % 3) * STAGE_BYTES + sOff;
        const uint32_t sB = sA + 16384;
        const char* Ap = gA[ph] + kt2;
        const char* Bp = gB[ph] + kt2;
#pragma unroll
        for (int i = 0; i < 4; ++i) {
            CP_ASYNC16(sA + i * 4096, Ap + i * aStride[ph]);
            CP_ASYNC16(sB + i * 4096, Bp + i * bStride[ph]);
        }
    };

    issue_loads(0); CP_COMMIT();
    issue_loads(1); CP_COMMIT();

#pragma unroll 1
    for (int it = 0; it < T; ++it) {
        if (it + 1 < T) { CP_WAIT1(); } else { CP_WAIT0(); }
        __syncthreads();
        if (it + 2 < T) { issue_loads(it + 2); CP_COMMIT(); }

        const uint32_t sA = sb + (it % 3) * STAGE_BYTES;
        const uint32_t sB = sA + 16384;
#pragma unroll
        for (int kk = 0; kk < 4; ++kk) {
            uint32_t aF[4][4], bF[4][2];
            const uint32_t aCol = ((uint32_t)(kk * 32) + aCol0) ^ aXm;
            const uint32_t bCol = ((uint32_t)(kk * 32) + bCol0) ^ bXm;
#pragma unroll
            for (int mt = 0; mt < 4; ++mt)
                ldsm_x4(aF[mt], sA + aBase[mt] + aCol);
#pragma unroll
            for (int np = 0; np < 2; ++np) {
                uint32_t r4[4];
                ldsm_x4(r4, sB + bBase[np] + bCol);
                bF[2 * np][0] = r4[0]; bF[2 * np][1] = r4[1];
                bF[2 * np + 1][0] = r4[2]; bF[2 * np + 1][1] = r4[3];
            }
#pragma unroll
            for (int mt = 0; mt < 4; ++mt)
#pragma unroll
                for (int nt = 0; nt < 4; ++nt)
                    mma_fp16(acc[mt][nt], aF[mt], bF[nt]);
        }
    }

    const int gid = lane >> 2, tig = lane & 3;
#pragma unroll
    for (int mt = 0; mt < 4; ++mt) {
#pragma unroll
        for (int nt = 0; nt < 4; ++nt) {
            int col = n0 + wn * 32 + nt * 8 + 2 * tig;
            float2 bv = *reinterpret_cast<const float2*>(&bias[col]);
            int r0 = m0 + wm * 64 + mt * 16 + gid;
            float2 v0, v1;
            v0.x = acc[mt][nt][0] + bv.x; v0.y = acc[mt][nt][1] + bv.y;
            v1.x = acc[mt][nt][2] + bv.x; v1.y = acc[mt][nt][3] + bv.y;
            if (DO_TANH) {
                v0.x = tanhf(v0.x); v0.y = tanhf(v0.y);
                v1.x = tanhf(v1.x); v1.y = tanhf(v1.y);
            }
            *reinterpret_cast<float2*>(&C[(size_t)r0 * NG + col]) = v0;
            *reinterpret_cast<float2*>(&C[(size_t)(r0 + 8) * NG + col]) = v1;
        }
    }
}

// ---------------------------------------------------------------------------
extern "C" void kernel_launch(void* const* d_in, const int* in_sizes, int n_in,
                              void* d_out, int out_size)
{
    const float* x        = (const float*)d_in[0];
    const float* W_in     = (const float*)d_in[1];
    const float* b_in     = (const float*)d_in[2];
    const float* leak_tau = (const float*)d_in[3];
    const float* thr      = (const float*)d_in[4];
    const float* W_out    = (const float*)d_in[5];
    const float* b_out    = (const float*)d_in[6];
    float* out = (float*)d_out;

    float* pI; cudaGetSymbolAddress((void**)&pI, g_I);
    __half *xa, *xb, *c1, *Wi1, *Wi2, *Wo1;
    cudaGetSymbolAddress((void**)&xa,  g_xa);
    cudaGetSymbolAddress((void**)&xb,  g_xb);
    cudaGetSymbolAddress((void**)&c1,  g_c1);
    cudaGetSymbolAddress((void**)&Wi1, g_Wi1);
    cudaGetSymbolAddress((void**)&Wi2, g_Wi2);
    cudaGetSymbolAddress((void**)&Wo1, g_Wo1);

    cudaFuncSetAttribute(gemm_mma<3, 48, false>,
                         cudaFuncAttributeMaxDynamicSharedMemorySize, GEMM_SMEM);
    cudaFuncSetAttribute(gemm_mma<1, 32, true>,
                         cudaFuncAttributeMaxDynamicSharedMemorySize, GEMM_SMEM);

    // Splits (fp16 2-way; W_out only needs the primary fp16 image)
    split2_x<<<2048, 256>>>((const float4*)x, (__half2*)xa, (__half2*)xb,
                            (size_t)Msz * INsz / 4);
    transpose_split2<<<dim3(Hsz / 32, INsz / 32), dim3(32, 8)>>>(
        W_in, INsz, Hsz, Wi1, Wi2);
    transpose_split2<<<dim3(Hsz / 32, (2 * Hsz) / 32), dim3(32, 8)>>>(
        W_out, 2 * Hsz, Hsz, Wo1, nullptr);

    // GEMM1: I = x @ W_in + b_in — 3-term fp16 split, small terms first:
    //   (2,1) xb*Wi1, (1,2) xa*Wi2, (1,1) xa*Wi1  (16 iters each)
    //   (Pre-threshold: residual terms REQUIRED — flip amplification.)
    {
        GemmSpec g = {};
        const __half* As[3] = { xb,  xa,  xa  };
        const __half* Bs[3] = { Wi1, Wi2, Wi1 };
        for (int p = 0; p < 3; ++p) {
            g.A[p] = As[p]; g.B[p] = Bs[p];
            g.lda[p] = INsz; g.ldb[p] = INsz;
            g.cum[p] = p * 16;
        }
        g.cum[3] = 48;
        gemm_mma<3, 48, false><<<dim3(Hsz / 128, Msz / 128), 256, GEMM_SMEM>>>(
            g, b_in, pI);
    }

    // Chunked parallel scan -> c1
    {
        dim3 gc(Hsz / 256, Bsz, NC);
        dim3 gs(Hsz / 256, Bsz, 1);
        scan_s1<<<gc, 256>>>(leak_tau);
        scan_s2<<<gs, 256>>>(leak_tau);
        scan_s3<<<gc, 256>>>(leak_tau, thr);
        scan_s4<<<gs, 256>>>();
        scan_s5<<<gc, 256>>>();
    }

    // GEMM2: out = tanh(c1 @ Wo1^T + b_out) — single plain fp16 GEMM
    // (both residual terms dropped; calibrated post-trigger error calculus).
    {
        GemmSpec g = {};
        g.A[0] = c1; g.B[0] = Wo1; g.lda[0] = 2048; g.ldb[0] = 2048;
        g.A[1] = c1; g.B[1] = Wo1; g.lda[1] = 2048; g.ldb[1] = 2048; // unused
        g.A[2] = c1; g.B[2] = Wo1; g.lda[2] = 2048; g.ldb[2] = 2048; // unused
        g.cum[0] = 0; g.cum[1] = 32; g.cum[2] = 32; g.cum[3] = 32;
        gemm_mma<1, 32, true><<<dim3(NG / 128, Msz / 128), 256, GEMM_SMEM>>>(
            g, b_out, out);
    }
}

// round 16
// speedup vs baseline: 1.0962x; 1.0184x over previous
#include <cuda_runtime.h>
#include <cuda_fp16.h>
#include <stdint.h>
#include <math.h>

// ---------------------------------------------------------------------------
// Problem dims
// ---------------------------------------------------------------------------
namespace {
constexpr int Bsz  = 16;
constexpr int Ssz  = 2048;
constexpr int Hsz  = 1024;
constexpr int INsz = 1024;
constexpr int Msz  = Bsz * Ssz;       // 32768
constexpr int NG   = 1024;
constexpr int STAGE_BYTES = 32768;    // 16KB A + 16KB B per stage
constexpr int GEMM_SMEM = 3 * STAGE_BYTES;  // 96 KiB, 3-stage ring, 2 CTA/SM
constexpr int NC   = 32;              // scan chunks
constexpr int CL   = Ssz / NC;        // 64 timesteps per chunk
}

// ---------------------------------------------------------------------------
// Scratch (__device__ globals; no allocation allowed)
// ---------------------------------------------------------------------------
__device__ float g_I[(size_t)Msz * Hsz];                   // 128 MiB
__device__ __half g_xa[(size_t)Msz * INsz];                // x 2-way fp16 split
__device__ __half g_xb[(size_t)Msz * INsz];
__device__ __half g_c1[(size_t)Msz * 2 * Hsz];             // [M][2048]: v | s
__device__ __half g_Wi1[(size_t)Hsz * INsz];               // W_in^T fp16 splits [N][K]
__device__ __half g_Wi2[(size_t)Hsz * INsz];
__device__ __half g_Wo1[(size_t)Hsz * 2 * Hsz];            // W_out^T fp16 [N][2048]
// scan pipeline scratch: [c][b][h]
__device__ float g_vend [(size_t)NC * Bsz * Hsz];
__device__ float g_vinit[(size_t)NC * Bsz * Hsz];
__device__ int   g_fc   [(size_t)NC * Bsz * Hsz];
__device__ float g_ls   [(size_t)NC * Bsz * Hsz];
__device__ float g_sinit[(size_t)NC * Bsz * Hsz];

// ---------------------------------------------------------------------------
// PTX helpers (base sm_80+ features only)
// ---------------------------------------------------------------------------
#define SWZ128(o) ((o) ^ (((o) >> 3) & 0x70))

__device__ __forceinline__ uint32_t smem_u32(const void* p) {
    uint32_t a;
    asm("{ .reg .u64 t; cvta.to.shared.u64 t, %1; cvt.u32.u64 %0, t; }"
        : "=r"(a) : "l"(p));
    return a;
}
#define CP_ASYNC16(s, g) \
    asm volatile("cp.async.cg.shared.global [%0], [%1], 16;" :: "r"(s), "l"(g))
#define CP_COMMIT()  asm volatile("cp.async.commit_group;" ::: "memory")
#define CP_WAIT0()   asm volatile("cp.async.wait_group 0;" ::: "memory")
#define CP_WAIT1()   asm volatile("cp.async.wait_group 1;" ::: "memory")

__device__ __forceinline__ void ldsm_x4(uint32_t r[4], uint32_t addr) {
    asm volatile("ldmatrix.sync.aligned.m8n8.x4.shared.b16 {%0,%1,%2,%3}, [%4];"
        : "=r"(r[0]), "=r"(r[1]), "=r"(r[2]), "=r"(r[3]) : "r"(addr));
}
__device__ __forceinline__ void mma_fp16(float c[4], const uint32_t a[4],
                                         const uint32_t b[2]) {
    asm volatile(
        "mma.sync.aligned.m16n8k16.row.col.f32.f16.f16.f32 "
        "{%0,%1,%2,%3}, {%4,%5,%6,%7}, {%8,%9}, {%0,%1,%2,%3};"
        : "+f"(c[0]), "+f"(c[1]), "+f"(c[2]), "+f"(c[3])
        : "r"(a[0]), "r"(a[1]), "r"(a[2]), "r"(a[3]), "r"(b[0]), "r"(b[1]));
}
// Fast tanh via MUFU.TANH (sm_75+); max rel err ~2^-11, RMS ~1e-4.
__device__ __forceinline__ float tanh_fast(float x) {
    float y;
    asm("tanh.approx.f32 %0, %1;" : "=f"(y) : "f"(x));
    return y;
}

// ---------------------------------------------------------------------------
// Split kernels (fp16 2-way), vectorized
// ---------------------------------------------------------------------------
__global__ void split2_x(const float4* __restrict__ x4, __half2* __restrict__ o1,
                         __half2* __restrict__ o2, size_t n4)
{
    size_t i = (size_t)blockIdx.x * blockDim.x + threadIdx.x;
    size_t stride = (size_t)gridDim.x * blockDim.x;
    for (; i < n4; i += stride) {
        float4 w = x4[i];
        __half a0 = __float2half_rn(w.x), a1 = __float2half_rn(w.y);
        __half a2 = __float2half_rn(w.z), a3 = __float2half_rn(w.w);
        o1[2 * i]     = __halves2half2(a0, a1);
        o1[2 * i + 1] = __halves2half2(a2, a3);
        o2[2 * i]     = __halves2half2(
            __float2half_rn(w.x - __half2float(a0)),
            __float2half_rn(w.y - __half2float(a1)));
        o2[2 * i + 1] = __halves2half2(
            __float2half_rn(w.z - __half2float(a2)),
            __float2half_rn(w.w - __half2float(a3)));
    }
}

// W[K][N] fp32 -> o[N][K] fp16 2-way split (o2 optional)
__global__ void transpose_split2(const float* __restrict__ W, int K, int N,
                                 __half* __restrict__ o1,
                                 __half* __restrict__ o2)
{
    __shared__ float t[32][33];
    int n0 = blockIdx.x * 32, k0 = blockIdx.y * 32;
    int tx = threadIdx.x, ty = threadIdx.y;   // (32, 8)
#pragma unroll
    for (int i = 0; i < 4; ++i)
        t[ty + i * 8][tx] = W[(size_t)(k0 + ty + i * 8) * N + n0 + tx];
    __syncthreads();
#pragma unroll
    for (int i = 0; i < 4; ++i) {
        int nn = n0 + ty + i * 8, k = k0 + tx;
        float w = t[tx][ty + i * 8];
        __half a = __float2half_rn(w);
        o1[(size_t)nn * K + k] = a;
        if (o2) {
            float r = w - __half2float(a);
            o2[(size_t)nn * K + k] = __float2half_rn(r);
        }
    }
}

// ---------------------------------------------------------------------------
// Chunked parallel hysteresis scan (proven in R8).
// ---------------------------------------------------------------------------
__device__ __forceinline__ float sig_alpha(const float* lt, int h) {
    return 1.0f / (1.0f + expf(lt[h]));
}

__global__ void scan_s1(const float* __restrict__ leak_tau)
{
    const int h = blockIdx.x * blockDim.x + threadIdx.x;
    const int b = blockIdx.y, c = blockIdx.z;
    const float alpha = sig_alpha(leak_tau, h);
    const float* Ip = g_I + ((size_t)b * Ssz + c * CL) * Hsz + h;
    float v = 0.0f;
#pragma unroll 4
    for (int t = 0; t < CL; ++t)
        v = fmaf(alpha, v, Ip[(size_t)t * Hsz]);
    g_vend[((size_t)c * Bsz + b) * Hsz + h] = v;
}

__global__ void scan_s2(const float* __restrict__ leak_tau)
{
    const int h = blockIdx.x * blockDim.x + threadIdx.x;
    const int b = blockIdx.y;
    const float alpha = sig_alpha(leak_tau, h);
    const float aL = powf(alpha, (float)CL);
    float v = 0.0f;
    for (int c = 0; c < NC; ++c) {
        size_t o = ((size_t)c * Bsz + b) * Hsz + h;
        g_vinit[o] = v;
        v = fmaf(aL, v, g_vend[o]);
    }
}

__global__ void scan_s3(const float* __restrict__ leak_tau,
                        const float* __restrict__ thr_arr)
{
    const int h = blockIdx.x * blockDim.x + threadIdx.x;
    const int b = blockIdx.y, c = blockIdx.z;
    const float alpha = sig_alpha(leak_tau, h);
    const float th = thr_arr[h];
    const size_t co = ((size_t)c * Bsz + b) * Hsz + h;
    float v = g_vinit[co];

    const int t0 = c * CL;
    const float* Ip = g_I + ((size_t)b * Ssz + t0) * Hsz + h;
    __half* c1 = g_c1 + ((size_t)b * Ssz + t0) * 2 * Hsz + h;

    int fc = CL;
    float s = 0.0f;
#pragma unroll 4
    for (int t = 0; t < CL; ++t) {
        v = fmaf(alpha, v, Ip[(size_t)t * Hsz]);
        bool up = v > th, dn = v < -th;
        if (up | dn) {
            if (fc == CL) fc = t;
            s = up ? 1.0f : -1.0f;
        }
        c1[(size_t)t * 2 * Hsz] = __float2half_rn(v);
        if (fc != CL)
            c1[(size_t)t * 2 * Hsz + Hsz] = __float2half_rn(s);
    }
    g_fc[co] = fc;
    g_ls[co] = s;
}

__global__ void scan_s4()
{
    const int h = blockIdx.x * blockDim.x + threadIdx.x;
    const int b = blockIdx.y;
    float s = -1.0f;
    for (int c = 0; c < NC; ++c) {
        size_t o = ((size_t)c * Bsz + b) * Hsz + h;
        g_sinit[o] = s;
        if (g_fc[o] < CL) s = g_ls[o];
    }
}

__global__ void scan_s5()
{
    const int h = blockIdx.x * blockDim.x + threadIdx.x;
    const int b = blockIdx.y, c = blockIdx.z;
    const size_t co = ((size_t)c * Bsz + b) * Hsz + h;
    const int fc = g_fc[co];
    if (fc == 0) return;
    const __half sv = __float2half_rn(g_sinit[co]);
    __half* c1s = g_c1 + ((size_t)b * Ssz + c * CL) * 2 * Hsz + Hsz + h;
    for (int t = 0; t < fc; ++t)
        c1s[(size_t)t * 2 * Hsz] = sv;
}

// ---------------------------------------------------------------------------
// Multi-phase fp16 split-GEMM on mma.sync (R12 config: CTA 128x128, 8 warps
// 2x4, warp tile 64x32, 3-stage ring, 2 CTA/SM — proven optimum).
// Precomputed cp.async addressing with 32-bit strides (R15).
// ---------------------------------------------------------------------------
struct GemmSpec {
    const __half* A[3];
    const __half* B[3];
    int lda[3];
    int ldb[3];
    int cum[4];
};

template<int NPH, int T, bool DO_TANH>
__global__ __launch_bounds__(256, 2)
void gemm_mma(const __grid_constant__ GemmSpec spec,
              const float* __restrict__ bias, float* __restrict__ C)
{
    extern __shared__ __align__(1024) char smem[];
    const uint32_t sb = smem_u32(smem);
    const int tid = threadIdx.x, lane = tid & 31, wid = tid >> 5;
    const int wm = wid >> 2, wn = wid & 3;
    const int m0 = blockIdx.y * 128, n0 = blockIdx.x * 128;

    float acc[4][4][4];
#pragma unroll
    for (int i = 0; i < 4; ++i)
#pragma unroll
        for (int j = 0; j < 4; ++j)
#pragma unroll
            for (int k = 0; k < 4; ++k) acc[i][j][k] = 0.0f;

    // --- Precomputed cp.async addressing (32-bit strides) ---------------
    const int ldr = tid >> 3;
    const int ldc = (tid & 7) * 16;
    const uint32_t sOff = (uint32_t)SWZ128(ldr * 128 + ldc);
    const char* gA[NPH]; const char* gB[NPH];
    int aStride[NPH], bStride[NPH];
#pragma unroll
    for (int p = 0; p < NPH; ++p) {
        gA[p] = (const char*)spec.A[p] + ((size_t)(m0 + ldr) * spec.lda[p]) * 2 + ldc;
        gB[p] = (const char*)spec.B[p] + ((size_t)(n0 + ldr) * spec.ldb[p]) * 2 + ldc;
        aStride[p] = 32 * spec.lda[p] * 2;
        bStride[p] = 32 * spec.ldb[p] * 2;
    }

    // Hoisted LDSM addressing: offset = row*128 + (col ^ ((row&7)<<4)).
    uint32_t aBase[4], aXm;
    {
        int r0 = wm * 64 + (lane & 15);
#pragma unroll
        for (int mt = 0; mt < 4; ++mt) aBase[mt] = (uint32_t)((r0 + mt * 16) * 128);
        aXm = (uint32_t)(((r0 & 7) << 4));
    }
    const uint32_t aCol0 = (uint32_t)((lane >> 4) * 16);
    uint32_t bBase[2], bXm;
    {
        int mat = lane >> 3;
        int rb = wn * 32 + (mat >> 1) * 8 + (lane & 7);
#pragma unroll
        for (int np = 0; np < 2; ++np) bBase[np] = (uint32_t)((rb + np * 16) * 128);
        bXm = (uint32_t)(((rb & 7) << 4));
    }
    const uint32_t bCol0 = (uint32_t)(((lane >> 3) & 1) * 16);

    auto issue_loads = [&](int it) {
        int ph = 0;
#pragma unroll
        for (int p = 0; p < NPH - 1; ++p) if (it >= spec.cum[p + 1]) ph = p + 1;
        const int kt2 = (it - spec.cum[ph]) * 128;  // 64 elem * 2B
        const uint32_t sA = sb + (it % 3) * STAGE_BYTES + sOff;
        const uint32_t sB = sA + 16384;
        const char* Ap = gA[ph] + kt2;
        const char* Bp = gB[ph] + kt2;
        const int as = aStride[ph], bs = bStride[ph];
#pragma unroll
        for (int i = 0; i < 4; ++i) {
            CP_ASYNC16(sA + i * 4096, Ap + i * as);
            CP_ASYNC16(sB + i * 4096, Bp + i * bs);
        }
    };

    issue_loads(0); CP_COMMIT();
    issue_loads(1); CP_COMMIT();

#pragma unroll 1
    for (int it = 0; it < T; ++it) {
        if (it + 1 < T) { CP_WAIT1(); } else { CP_WAIT0(); }
        __syncthreads();
        if (it + 2 < T) { issue_loads(it + 2); CP_COMMIT(); }

        const uint32_t sA = sb + (it % 3) * STAGE_BYTES;
        const uint32_t sB = sA + 16384;
#pragma unroll
        for (int kk = 0; kk < 4; ++kk) {
            uint32_t aF[4][4], bF[4][2];
            const uint32_t aCol = ((uint32_t)(kk * 32) + aCol0) ^ aXm;
            const uint32_t bCol = ((uint32_t)(kk * 32) + bCol0) ^ bXm;
#pragma unroll
            for (int mt = 0; mt < 4; ++mt)
                ldsm_x4(aF[mt], sA + aBase[mt] + aCol);
#pragma unroll
            for (int np = 0; np < 2; ++np) {
                uint32_t r4[4];
                ldsm_x4(r4, sB + bBase[np] + bCol);
                bF[2 * np][0] = r4[0]; bF[2 * np][1] = r4[1];
                bF[2 * np + 1][0] = r4[2]; bF[2 * np + 1][1] = r4[3];
            }
#pragma unroll
            for (int mt = 0; mt < 4; ++mt)
#pragma unroll
                for (int nt = 0; nt < 4; ++nt)
                    mma_fp16(acc[mt][nt], aF[mt], bF[nt]);
        }
    }

    const int gid = lane >> 2, tig = lane & 3;
#pragma unroll
    for (int mt = 0; mt < 4; ++mt) {
#pragma unroll
        for (int nt = 0; nt < 4; ++nt) {
            int col = n0 + wn * 32 + nt * 8 + 2 * tig;
            float2 bv = *reinterpret_cast<const float2*>(&bias[col]);
            int r0 = m0 + wm * 64 + mt * 16 + gid;
            float2 v0, v1;
            v0.x = acc[mt][nt][0] + bv.x; v0.y = acc[mt][nt][1] + bv.y;
            v1.x = acc[mt][nt][2] + bv.x; v1.y = acc[mt][nt][3] + bv.y;
            if (DO_TANH) {
                v0.x = tanh_fast(v0.x); v0.y = tanh_fast(v0.y);
                v1.x = tanh_fast(v1.x); v1.y = tanh_fast(v1.y);
            }
            *reinterpret_cast<float2*>(&C[(size_t)r0 * NG + col]) = v0;
            *reinterpret_cast<float2*>(&C[(size_t)(r0 + 8) * NG + col]) = v1;
        }
    }
}

// ---------------------------------------------------------------------------
extern "C" void kernel_launch(void* const* d_in, const int* in_sizes, int n_in,
                              void* d_out, int out_size)
{
    const float* x        = (const float*)d_in[0];
    const float* W_in     = (const float*)d_in[1];
    const float* b_in     = (const float*)d_in[2];
    const float* leak_tau = (const float*)d_in[3];
    const float* thr      = (const float*)d_in[4];
    const float* W_out    = (const float*)d_in[5];
    const float* b_out    = (const float*)d_in[6];
    float* out = (float*)d_out;

    float* pI; cudaGetSymbolAddress((void**)&pI, g_I);
    __half *xa, *xb, *c1, *Wi1, *Wi2, *Wo1;
    cudaGetSymbolAddress((void**)&xa,  g_xa);
    cudaGetSymbolAddress((void**)&xb,  g_xb);
    cudaGetSymbolAddress((void**)&c1,  g_c1);
    cudaGetSymbolAddress((void**)&Wi1, g_Wi1);
    cudaGetSymbolAddress((void**)&Wi2, g_Wi2);
    cudaGetSymbolAddress((void**)&Wo1, g_Wo1);

    cudaFuncSetAttribute(gemm_mma<3, 48, false>,
                         cudaFuncAttributeMaxDynamicSharedMemorySize, GEMM_SMEM);
    cudaFuncSetAttribute(gemm_mma<1, 32, true>,
                         cudaFuncAttributeMaxDynamicSharedMemorySize, GEMM_SMEM);

    // Splits (fp16 2-way; W_out only needs the primary fp16 image)
    split2_x<<<2048, 256>>>((const float4*)x, (__half2*)xa, (__half2*)xb,
                            (size_t)Msz * INsz / 4);
    transpose_split2<<<dim3(Hsz / 32, INsz / 32), dim3(32, 8)>>>(
        W_in, INsz, Hsz, Wi1, Wi2);
    transpose_split2<<<dim3(Hsz / 32, (2 * Hsz) / 32), dim3(32, 8)>>>(
        W_out, 2 * Hsz, Hsz, Wo1, nullptr);

    // GEMM1: I = x @ W_in + b_in — 3-term fp16 split, small terms first:
    //   (2,1) xb*Wi1, (1,2) xa*Wi2, (1,1) xa*Wi1  (16 iters each)
    //   (Pre-threshold: residual terms REQUIRED — flip amplification.)
    {
        GemmSpec g = {};
        const __half* As[3] = { xb,  xa,  xa  };
        const __half* Bs[3] = { Wi1, Wi2, Wi1 };
        for (int p = 0; p < 3; ++p) {
            g.A[p] = As[p]; g.B[p] = Bs[p];
            g.lda[p] = INsz; g.ldb[p] = INsz;
            g.cum[p] = p * 16;
        }
        g.cum[3] = 48;
        gemm_mma<3, 48, false><<<dim3(Hsz / 128, Msz / 128), 256, GEMM_SMEM>>>(
            g, b_in, pI);
    }

    // Chunked parallel scan -> c1
    {
        dim3 gc(Hsz / 256, Bsz, NC);
        dim3 gs(Hsz / 256, Bsz, 1);
        scan_s1<<<gc, 256>>>(leak_tau);
        scan_s2<<<gs, 256>>>(leak_tau);
        scan_s3<<<gc, 256>>>(leak_tau, thr);
        scan_s4<<<gs, 256>>>();
        scan_s5<<<gc, 256>>>();
    }

    // GEMM2: out = tanh(c1 @ Wo1^T + b_out) — single plain fp16 GEMM,
    // MUFU.TANH epilogue (RMS approx err ~1e-4, direct-to-output class).
    {
        GemmSpec g = {};
        g.A[0] = c1; g.B[0] = Wo1; g.lda[0] = 2048; g.ldb[0] = 2048;
        g.A[1] = c1; g.B[1] = Wo1; g.lda[1] = 2048; g.ldb[1] = 2048; // unused
        g.A[2] = c1; g.B[2] = Wo1; g.lda[2] = 2048; g.ldb[2] = 2048; // unused
        g.cum[0] = 0; g.cum[1] = 32; g.cum[2] = 32; g.cum[3] = 32;
        gemm_mma<1, 32, true><<<dim3(NG / 128, Msz / 128), 256, GEMM_SMEM>>>(
            g, b_out, out);
    }
}

// round 17
// speedup vs baseline: 1.1035x; 1.0066x over previous
#include <cuda_runtime.h>
#include <cuda_fp16.h>
#include <stdint.h>
#include <math.h>

// ---------------------------------------------------------------------------
// Problem dims
// ---------------------------------------------------------------------------
namespace {
constexpr int Bsz  = 16;
constexpr int Ssz  = 2048;
constexpr int Hsz  = 1024;
constexpr int INsz = 1024;
constexpr int Msz  = Bsz * Ssz;       // 32768
constexpr int NG   = 1024;
constexpr int STAGE_BYTES = 32768;    // 16KB A + 16KB B per stage
constexpr int GEMM_SMEM = 3 * STAGE_BYTES;  // 96 KiB, 3-stage ring, 2 CTA/SM
constexpr int NC   = 32;              // scan chunks
constexpr int CL   = Ssz / NC;        // 64 timesteps per chunk
}

// ---------------------------------------------------------------------------
// Scratch (__device__ globals; no allocation allowed)
// ---------------------------------------------------------------------------
__device__ float g_I[(size_t)Msz * Hsz];                   // 128 MiB
__device__ __half g_xa[(size_t)Msz * INsz];                // x 2-way fp16 split
__device__ __half g_xb[(size_t)Msz * INsz];
__device__ __half g_c1[(size_t)Msz * 2 * Hsz];             // [M][2048]: v | s
__device__ __half g_Wi1[(size_t)Hsz * INsz];               // W_in^T fp16 splits [N][K]
__device__ __half g_Wi2[(size_t)Hsz * INsz];
__device__ __half g_Wo1[(size_t)Hsz * 2 * Hsz];            // W_out^T fp16 [N][2048]
// scan pipeline scratch: [c][b][h]
__device__ float g_vend [(size_t)NC * Bsz * Hsz];
__device__ float g_vinit[(size_t)NC * Bsz * Hsz];
__device__ int   g_fc   [(size_t)NC * Bsz * Hsz];
__device__ float g_ls   [(size_t)NC * Bsz * Hsz];
__device__ float g_sinit[(size_t)NC * Bsz * Hsz];

// ---------------------------------------------------------------------------
// PTX helpers (base sm_80+ features only)
// ---------------------------------------------------------------------------
#define SWZ128(o) ((o) ^ (((o) >> 3) & 0x70))

__device__ __forceinline__ uint32_t smem_u32(const void* p) {
    uint32_t a;
    asm("{ .reg .u64 t; cvta.to.shared.u64 t, %1; cvt.u32.u64 %0, t; }"
        : "=r"(a) : "l"(p));
    return a;
}
#define CP_ASYNC16(s, g) \
    asm volatile("cp.async.cg.shared.global [%0], [%1], 16;" :: "r"(s), "l"(g))
#define CP_COMMIT()  asm volatile("cp.async.commit_group;" ::: "memory")
#define CP_WAIT0()   asm volatile("cp.async.wait_group 0;" ::: "memory")
#define CP_WAIT1()   asm volatile("cp.async.wait_group 1;" ::: "memory")

__device__ __forceinline__ void ldsm_x4(uint32_t r[4], uint32_t addr) {
    asm volatile("ldmatrix.sync.aligned.m8n8.x4.shared.b16 {%0,%1,%2,%3}, [%4];"
        : "=r"(r[0]), "=r"(r[1]), "=r"(r[2]), "=r"(r[3]) : "r"(addr));
}
__device__ __forceinline__ void mma_fp16(float c[4], const uint32_t a[4],
                                         const uint32_t b[2]) {
    asm volatile(
        "mma.sync.aligned.m16n8k16.row.col.f32.f16.f16.f32 "
        "{%0,%1,%2,%3}, {%4,%5,%6,%7}, {%8,%9}, {%0,%1,%2,%3};"
        : "+f"(c[0]), "+f"(c[1]), "+f"(c[2]), "+f"(c[3])
        : "r"(a[0]), "r"(a[1]), "r"(a[2]), "r"(a[3]), "r"(b[0]), "r"(b[1]));
}
// Fast tanh via MUFU.TANH (sm_75+); verified: adds ~1e-8 to rel_err.
__device__ __forceinline__ float tanh_fast(float x) {
    float y;
    asm("tanh.approx.f32 %0, %1;" : "=f"(y) : "f"(x));
    return y;
}

// ---------------------------------------------------------------------------
// Split kernels (fp16 2-way), vectorized
// ---------------------------------------------------------------------------
__global__ void split2_x(const float4* __restrict__ x4, __half2* __restrict__ o1,
                         __half2* __restrict__ o2, size_t n4)
{
    size_t i = (size_t)blockIdx.x * blockDim.x + threadIdx.x;
    size_t stride = (size_t)gridDim.x * blockDim.x;
    for (; i < n4; i += stride) {
        float4 w = x4[i];
        __half a0 = __float2half_rn(w.x), a1 = __float2half_rn(w.y);
        __half a2 = __float2half_rn(w.z), a3 = __float2half_rn(w.w);
        o1[2 * i]     = __halves2half2(a0, a1);
        o1[2 * i + 1] = __halves2half2(a2, a3);
        o2[2 * i]     = __halves2half2(
            __float2half_rn(w.x - __half2float(a0)),
            __float2half_rn(w.y - __half2float(a1)));
        o2[2 * i + 1] = __halves2half2(
            __float2half_rn(w.z - __half2float(a2)),
            __float2half_rn(w.w - __half2float(a3)));
    }
}

// W[K][N] fp32 -> o[N][K] fp16 2-way split (o2 optional)
__global__ void transpose_split2(const float* __restrict__ W, int K, int N,
                                 __half* __restrict__ o1,
                                 __half* __restrict__ o2)
{
    __shared__ float t[32][33];
    int n0 = blockIdx.x * 32, k0 = blockIdx.y * 32;
    int tx = threadIdx.x, ty = threadIdx.y;   // (32, 8)
#pragma unroll
    for (int i = 0; i < 4; ++i)
        t[ty + i * 8][tx] = W[(size_t)(k0 + ty + i * 8) * N + n0 + tx];
    __syncthreads();
#pragma unroll
    for (int i = 0; i < 4; ++i) {
        int nn = n0 + ty + i * 8, k = k0 + tx;
        float w = t[tx][ty + i * 8];
        __half a = __float2half_rn(w);
        o1[(size_t)nn * K + k] = a;
        if (o2) {
            float r = w - __half2float(a);
            o2[(size_t)nn * K + k] = __float2half_rn(r);
        }
    }
}

// ---------------------------------------------------------------------------
// Chunked parallel hysteresis scan (s1 fused into GEMM1 epilogue in R17).
// ---------------------------------------------------------------------------
__device__ __forceinline__ float sig_alpha(const float* lt, int h) {
    return 1.0f / (1.0f + expf(lt[h]));
}

__global__ void scan_s2(const float* __restrict__ leak_tau)
{
    const int h = blockIdx.x * blockDim.x + threadIdx.x;
    const int b = blockIdx.y;
    const float alpha = sig_alpha(leak_tau, h);
    const float aL = powf(alpha, (float)CL);
    float v = 0.0f;
    for (int c = 0; c < NC; ++c) {
        size_t o = ((size_t)c * Bsz + b) * Hsz + h;
        g_vinit[o] = v;
        v = fmaf(aL, v, g_vend[o]);
    }
}

__global__ void scan_s3(const float* __restrict__ leak_tau,
                        const float* __restrict__ thr_arr)
{
    const int h = blockIdx.x * blockDim.x + threadIdx.x;
    const int b = blockIdx.y, c = blockIdx.z;
    const float alpha = sig_alpha(leak_tau, h);
    const float th = thr_arr[h];
    const size_t co = ((size_t)c * Bsz + b) * Hsz + h;
    float v = g_vinit[co];

    const int t0 = c * CL;
    const float* Ip = g_I + ((size_t)b * Ssz + t0) * Hsz + h;
    __half* c1 = g_c1 + ((size_t)b * Ssz + t0) * 2 * Hsz + h;

    int fc = CL;
    float s = 0.0f;
#pragma unroll 4
    for (int t = 0; t < CL; ++t) {
        v = fmaf(alpha, v, Ip[(size_t)t * Hsz]);
        bool up = v > th, dn = v < -th;
        if (up | dn) {
            if (fc == CL) fc = t;
            s = up ? 1.0f : -1.0f;
        }
        c1[(size_t)t * 2 * Hsz] = __float2half_rn(v);
        if (fc != CL)
            c1[(size_t)t * 2 * Hsz + Hsz] = __float2half_rn(s);
    }
    g_fc[co] = fc;
    g_ls[co] = s;
}

__global__ void scan_s4()
{
    const int h = blockIdx.x * blockDim.x + threadIdx.x;
    const int b = blockIdx.y;
    float s = -1.0f;
    for (int c = 0; c < NC; ++c) {
        size_t o = ((size_t)c * Bsz + b) * Hsz + h;
        g_sinit[o] = s;
        if (g_fc[o] < CL) s = g_ls[o];
    }
}

__global__ void scan_s5()
{
    const int h = blockIdx.x * blockDim.x + threadIdx.x;
    const int b = blockIdx.y, c = blockIdx.z;
    const size_t co = ((size_t)c * Bsz + b) * Hsz + h;
    const int fc = g_fc[co];
    if (fc == 0) return;
    const __half sv = __float2half_rn(g_sinit[co]);
    __half* c1s = g_c1 + ((size_t)b * Ssz + c * CL) * 2 * Hsz + Hsz + h;
    for (int t = 0; t < fc; ++t)
        c1s[(size_t)t * 2 * Hsz] = sv;
}

// ---------------------------------------------------------------------------
// Multi-phase fp16 split-GEMM on mma.sync (R12 config: CTA 128x128, 8 warps
// 2x4, warp tile 64x32, 3-stage ring, 2 CTA/SM — proven optimum).
// R17: DO_SCAN1 fuses scan_s1 — the 128-row tile is exactly 2 scan chunks of
// one batch; stage post-bias I in the (free) smem ring, run 64-step chains,
// write g_vend. Bit-identical to the standalone scan_s1.
// ---------------------------------------------------------------------------
struct GemmSpec {
    const __half* A[3];
    const __half* B[3];
    int lda[3];
    int ldb[3];
    int cum[4];
};

template<int NPH, int T, bool DO_TANH, bool DO_SCAN1>
__global__ __launch_bounds__(256, 2)
void gemm_mma(const __grid_constant__ GemmSpec spec,
              const float* __restrict__ bias, float* __restrict__ C,
              const float* __restrict__ leak_tau)
{
    extern __shared__ __align__(1024) char smem[];
    const uint32_t sb = smem_u32(smem);
    const int tid = threadIdx.x, lane = tid & 31, wid = tid >> 5;
    const int wm = wid >> 2, wn = wid & 3;
    const int m0 = blockIdx.y * 128, n0 = blockIdx.x * 128;

    float acc[4][4][4];
#pragma unroll
    for (int i = 0; i < 4; ++i)
#pragma unroll
        for (int j = 0; j < 4; ++j)
#pragma unroll
            for (int k = 0; k < 4; ++k) acc[i][j][k] = 0.0f;

    // --- Precomputed cp.async addressing (32-bit strides) ---------------
    const int ldr = tid >> 3;
    const int ldc = (tid & 7) * 16;
    const uint32_t sOff = (uint32_t)SWZ128(ldr * 128 + ldc);
    const char* gA[NPH]; const char* gB[NPH];
    int aStride[NPH], bStride[NPH];
#pragma unroll
    for (int p = 0; p < NPH; ++p) {
        gA[p] = (const char*)spec.A[p] + ((size_t)(m0 + ldr) * spec.lda[p]) * 2 + ldc;
        gB[p] = (const char*)spec.B[p] + ((size_t)(n0 + ldr) * spec.ldb[p]) * 2 + ldc;
        aStride[p] = 32 * spec.lda[p] * 2;
        bStride[p] = 32 * spec.ldb[p] * 2;
    }

    // Hoisted LDSM addressing: offset = row*128 + (col ^ ((row&7)<<4)).
    uint32_t aBase[4], aXm;
    {
        int r0 = wm * 64 + (lane & 15);
#pragma unroll
        for (int mt = 0; mt < 4; ++mt) aBase[mt] = (uint32_t)((r0 + mt * 16) * 128);
        aXm = (uint32_t)(((r0 & 7) << 4));
    }
    const uint32_t aCol0 = (uint32_t)((lane >> 4) * 16);
    uint32_t bBase[2], bXm;
    {
        int mat = lane >> 3;
        int rb = wn * 32 + (mat >> 1) * 8 + (lane & 7);
#pragma unroll
        for (int np = 0; np < 2; ++np) bBase[np] = (uint32_t)((rb + np * 16) * 128);
        bXm = (uint32_t)(((rb & 7) << 4));
    }
    const uint32_t bCol0 = (uint32_t)(((lane >> 3) & 1) * 16);

    auto issue_loads = [&](int it) {
        int ph = 0;
#pragma unroll
        for (int p = 0; p < NPH - 1; ++p) if (it >= spec.cum[p + 1]) ph = p + 1;
        const int kt2 = (it - spec.cum[ph]) * 128;  // 64 elem * 2B
        const uint32_t sA = sb + (it % 3) * STAGE_BYTES + sOff;
        const uint32_t sB = sA + 16384;
        const char* Ap = gA[ph] + kt2;
        const char* Bp = gB[ph] + kt2;
        const int as = aStride[ph], bs = bStride[ph];
#pragma unroll
        for (int i = 0; i < 4; ++i) {
            CP_ASYNC16(sA + i * 4096, Ap + i * as);
            CP_ASYNC16(sB + i * 4096, Bp + i * bs);
        }
    };

    issue_loads(0); CP_COMMIT();
    issue_loads(1); CP_COMMIT();

#pragma unroll 1
    for (int it = 0; it < T; ++it) {
        if (it + 1 < T) { CP_WAIT1(); } else { CP_WAIT0(); }
        __syncthreads();
        if (it + 2 < T) { issue_loads(it + 2); CP_COMMIT(); }

        const uint32_t sA = sb + (it % 3) * STAGE_BYTES;
        const uint32_t sB = sA + 16384;
#pragma unroll
        for (int kk = 0; kk < 4; ++kk) {
            uint32_t aF[4][4], bF[4][2];
            const uint32_t aCol = ((uint32_t)(kk * 32) + aCol0) ^ aXm;
            const uint32_t bCol = ((uint32_t)(kk * 32) + bCol0) ^ bXm;
#pragma unroll
            for (int mt = 0; mt < 4; ++mt)
                ldsm_x4(aF[mt], sA + aBase[mt] + aCol);
#pragma unroll
            for (int np = 0; np < 2; ++np) {
                uint32_t r4[4];
                ldsm_x4(r4, sB + bBase[np] + bCol);
                bF[2 * np][0] = r4[0]; bF[2 * np][1] = r4[1];
                bF[2 * np + 1][0] = r4[2]; bF[2 * np + 1][1] = r4[3];
            }
#pragma unroll
            for (int mt = 0; mt < 4; ++mt)
#pragma unroll
                for (int nt = 0; nt < 4; ++nt)
                    mma_fp16(acc[mt][nt], aF[mt], bF[nt]);
        }
    }

    // Epilogue: bias (+tanh), float2 global stores; optionally stage post-bias
    // I into smem for the fused chunk-chain (scan_s1).
    constexpr int IPITCH = 132;   // floats per row (pad -> conflict-free chains)
    float* Ism = reinterpret_cast<float*>(smem);
    const int gid = lane >> 2, tig = lane & 3;
    if (DO_SCAN1) __syncthreads();   // mainloop smem reads done before overwrite
#pragma unroll
    for (int mt = 0; mt < 4; ++mt) {
#pragma unroll
        for (int nt = 0; nt < 4; ++nt) {
            int colL = wn * 32 + nt * 8 + 2 * tig;
            int col = n0 + colL;
            float2 bv = *reinterpret_cast<const float2*>(&bias[col]);
            int rL0 = wm * 64 + mt * 16 + gid;
            int r0 = m0 + rL0;
            float2 v0, v1;
            v0.x = acc[mt][nt][0] + bv.x; v0.y = acc[mt][nt][1] + bv.y;
            v1.x = acc[mt][nt][2] + bv.x; v1.y = acc[mt][nt][3] + bv.y;
            if (DO_SCAN1) {
                *reinterpret_cast<float2*>(&Ism[rL0 * IPITCH + colL]) = v0;
                *reinterpret_cast<float2*>(&Ism[(rL0 + 8) * IPITCH + colL]) = v1;
            }
            if (DO_TANH) {
                v0.x = tanh_fast(v0.x); v0.y = tanh_fast(v0.y);
                v1.x = tanh_fast(v1.x); v1.y = tanh_fast(v1.y);
            }
            *reinterpret_cast<float2*>(&C[(size_t)r0 * NG + col]) = v0;
            *reinterpret_cast<float2*>(&C[(size_t)(r0 + 8) * NG + col]) = v1;
        }
    }
    if (DO_SCAN1) {
        __syncthreads();
        // 256 threads -> 2 chunks x 128 cols; chain over 64 rows each.
        const int chunk = tid >> 7, colL = tid & 127;
        const int h = n0 + colL;
        const float alpha = 1.0f / (1.0f + expf(leak_tau[h]));
        const float* p = Ism + (chunk * CL) * IPITCH + colL;
        float v = 0.0f;
#pragma unroll 8
        for (int t = 0; t < CL; ++t)
            v = fmaf(alpha, v, p[t * IPITCH]);
        const int b = m0 >> 11;              // m0 / 2048
        const int c0 = (m0 & 2047) >> 6;     // (m0 % 2048) / 64
        g_vend[((size_t)(c0 + chunk) * Bsz + b) * Hsz + h] = v;
    }
}

// ---------------------------------------------------------------------------
extern "C" void kernel_launch(void* const* d_in, const int* in_sizes, int n_in,
                              void* d_out, int out_size)
{
    const float* x        = (const float*)d_in[0];
    const float* W_in     = (const float*)d_in[1];
    const float* b_in     = (const float*)d_in[2];
    const float* leak_tau = (const float*)d_in[3];
    const float* thr      = (const float*)d_in[4];
    const float* W_out    = (const float*)d_in[5];
    const float* b_out    = (const float*)d_in[6];
    float* out = (float*)d_out;

    float* pI; cudaGetSymbolAddress((void**)&pI, g_I);
    __half *xa, *xb, *c1, *Wi1, *Wi2, *Wo1;
    cudaGetSymbolAddress((void**)&xa,  g_xa);
    cudaGetSymbolAddress((void**)&xb,  g_xb);
    cudaGetSymbolAddress((void**)&c1,  g_c1);
    cudaGetSymbolAddress((void**)&Wi1, g_Wi1);
    cudaGetSymbolAddress((void**)&Wi2, g_Wi2);
    cudaGetSymbolAddress((void**)&Wo1, g_Wo1);

    cudaFuncSetAttribute(gemm_mma<3, 48, false, true>,
                         cudaFuncAttributeMaxDynamicSharedMemorySize, GEMM_SMEM);
    cudaFuncSetAttribute(gemm_mma<1, 32, true, false>,
                         cudaFuncAttributeMaxDynamicSharedMemorySize, GEMM_SMEM);

    // Splits (fp16 2-way; W_out only needs the primary fp16 image)
    split2_x<<<4096, 256>>>((const float4*)x, (__half2*)xa, (__half2*)xb,
                            (size_t)Msz * INsz / 4);
    transpose_split2<<<dim3(Hsz / 32, INsz / 32), dim3(32, 8)>>>(
        W_in, INsz, Hsz, Wi1, Wi2);
    transpose_split2<<<dim3(Hsz / 32, (2 * Hsz) / 32), dim3(32, 8)>>>(
        W_out, 2 * Hsz, Hsz, Wo1, nullptr);

    // GEMM1: I = x @ W_in + b_in — 3-term fp16 split, small terms first:
    //   (2,1) xb*Wi1, (1,2) xa*Wi2, (1,1) xa*Wi1  (16 iters each)
    //   + fused scan_s1 (per-tile chunk-chain -> g_vend).
    {
        GemmSpec g = {};
        const __half* As[3] = { xb,  xa,  xa  };
        const __half* Bs[3] = { Wi1, Wi2, Wi1 };
        for (int p = 0; p < 3; ++p) {
            g.A[p] = As[p]; g.B[p] = Bs[p];
            g.lda[p] = INsz; g.ldb[p] = INsz;
            g.cum[p] = p * 16;
        }
        g.cum[3] = 48;
        gemm_mma<3, 48, false, true><<<dim3(Hsz / 128, Msz / 128), 256, GEMM_SMEM>>>(
            g, b_in, pI, leak_tau);
    }

    // Chunked parallel scan (s1 fused above) -> c1
    {
        dim3 gc(Hsz / 256, Bsz, NC);
        dim3 gs(Hsz / 256, Bsz, 1);
        scan_s2<<<gs, 256>>>(leak_tau);
        scan_s3<<<gc, 256>>>(leak_tau, thr);
        scan_s4<<<gs, 256>>>();
        scan_s5<<<gc, 256>>>();
    }

    // GEMM2: out = tanh(c1 @ Wo1^T + b_out) — single plain fp16 GEMM,
    // MUFU.TANH epilogue.
    {
        GemmSpec g = {};
        g.A[0] = c1; g.B[0] = Wo1; g.lda[0] = 2048; g.ldb[0] = 2048;
        g.A[1] = c1; g.B[1] = Wo1; g.lda[1] = 2048; g.ldb[1] = 2048; // unused
        g.A[2] = c1; g.B[2] = Wo1; g.lda[2] = 2048; g.ldb[2] = 2048; // unused
        g.cum[0] = 0; g.cum[1] = 32; g.cum[2] = 32; g.cum[3] = 32;
        gemm_mma<1, 32, true, false><<<dim3(NG / 128, Msz / 128), 256, GEMM_SMEM>>>(
            g, b_out, out, nullptr);
    }
}